// round 4
// baseline (speedup 1.0000x reference)
#include <cuda_runtime.h>
#include <math.h>

#define B 16384
#define C 100
#define D 512
#define Z 128
#define BETA 50000000.0
#define EPSF 1e-8f

// accumulators: [0] = tube ds sum, [1] = -logp sum, [2] = kl term sum
// statically zeroed; last block resets after use -> graph-replay safe
__device__ double g_acc[3] = {0.0, 0.0, 0.0};
__device__ unsigned g_count = 0u;

__device__ __forceinline__ float warp_sum(float v) {
#pragma unroll
    for (int o = 16; o; o >>= 1) v += __shfl_xor_sync(0xffffffffu, v, o);
    return v;
}

// scalar tail of TUBE given full-row dot, |p|^2, |g|^2
__device__ __forceinline__ float tube_scalar(float dot, float pp, float gg) {
    float p = sqrtf(pp);
    float g = sqrtf(gg);
    float denom = p * g;
    float cosine = (denom == 0.f) ? 0.f : (dot / denom);
    float s_s = 1.f - cosine * cosine;
    float sine = (s_s < 0.f) ? 0.f : sqrtf((s_s <= 0.f) ? EPSF : s_s);
    float gd = (g == 0.f) ? (g + EPSF) : g;
    float pc = p * cosine;
    float r_all = pc / gd;
    float ps = p * sine;
    float ds;
    if (r_all >= 1.f)       ds = 0.5f * (ps + fabsf(g - pc));
    else if (r_all >= 0.f)  ds = ps + fabsf(g - pc);
    else                    ds = 1.5f * fabsf(pc - g - ps);
    return -__logf(tanhf(1.f / ds));   // ds==0 -> inf -> tanh=1 -> 0, matches jax
}

// 8 warps/block: warps 0-3 -> row0 pairs 0-3, warps 4-7 -> row1 pairs 0-3.
// pair-0 warp also computes KL for its row; pair-1 warp computes CE.
__global__ void __launch_bounds__(256, 6)
loss_kernel(const float* __restrict__ fusion,
            const float* __restrict__ comple,
            const float* __restrict__ labels,
            const float* __restrict__ lab_enc,
            const float* __restrict__ xA,  const float* __restrict__ xAr,
            const float* __restrict__ xB,  const float* __restrict__ xBr,
            const float* __restrict__ xC,  const float* __restrict__ xCr,
            const float* __restrict__ mu,  const float* __restrict__ lv,
            float* __restrict__ out)
{
    const int warp = threadIdx.x >> 5;
    const int lane = threadIdx.x & 31;
    const int pair = warp & 3;
    const int row  = blockIdx.x * 2 + (warp >> 2);
    const long rd  = (long)row * D;

    const float* att;
    const float* lab;
    if      (pair == 0) { att = xAr + rd;    lab = xA + rd; }
    else if (pair == 1) { att = xBr + rd;    lab = xB + rd; }
    else if (pair == 2) { att = xCr + rd;    lab = xC + rd; }
    else                { att = comple + rd; lab = lab_enc + rd; }

    // ---- tube pair: 8 front-batched LDG.128, 3 accumulators ----
    const float4* a4 = (const float4*)att;
    const float4* g4 = (const float4*)lab;
    float dot = 0.f, pp = 0.f, gg = 0.f;
#pragma unroll
    for (int i = 0; i < 4; i++) {
        float4 a = a4[lane + 32 * i];
        float4 g = g4[lane + 32 * i];
        dot += a.x * g.x + a.y * g.y + a.z * g.z + a.w * g.w;
        pp  += a.x * a.x + a.y * a.y + a.z * a.z + a.w * a.w;
        gg  += g.x * g.x + g.y * g.y + g.z * g.z + g.w * g.w;
    }

    float ce = 0.f, kl = 0.f;

    if (pair == 0) {
        // ---- KL: sum(1 + lv - mu^2 - exp(lv)) over Z=128 ----
        float4 m = ((const float4*)(mu + (long)row * Z))[lane];
        float4 l = ((const float4*)(lv + (long)row * Z))[lane];
        float k = (1.f + l.x - m.x * m.x - __expf(l.x))
                + (1.f + l.y - m.y * m.y - __expf(l.y))
                + (1.f + l.z - m.z * m.z - __expf(l.z))
                + (1.f + l.w - m.w * m.w - __expf(l.w));
        kl = warp_sum(k);
    } else if (pair == 1) {
        // ---- CE: -log_softmax(fusion)[argmax(labels)] ----
        const float* f  = fusion + (long)row * C;
        const float* lb = labels + (long)row * C;
        float fmax = -INFINITY;
        float lmax = -INFINITY;
        int   lidx = 0x7fffffff;
#pragma unroll
        for (int t = 0; t < 4; t++) {
            int i = lane + 32 * t;
            if (i < C) {
                float fv  = f[i];
                float lvv = lb[i];
                fmax = fmaxf(fmax, fv);
                if (lvv > lmax || (lvv == lmax && i < lidx)) { lmax = lvv; lidx = i; }
            }
        }
#pragma unroll
        for (int o = 16; o; o >>= 1) {
            fmax = fmaxf(fmax, __shfl_xor_sync(0xffffffffu, fmax, o));
            float ol = __shfl_xor_sync(0xffffffffu, lmax, o);
            int   oi = __shfl_xor_sync(0xffffffffu, lidx, o);
            if (ol > lmax || (ol == lmax && oi < lidx)) { lmax = ol; lidx = oi; }
        }
        float se = 0.f;
#pragma unroll
        for (int t = 0; t < 4; t++) {
            int i = lane + 32 * t;
            if (i < C) se += __expf(f[i] - fmax);  // L1 hit (pass 1 loaded it)
        }
        se = warp_sum(se);
        ce = -(f[lidx] - fmax - __logf(se));
    }

    // ---- tube reductions ----
    dot = warp_sum(dot);
    pp  = warp_sum(pp);
    gg  = warp_sum(gg);
    float tube = tube_scalar(dot, pp, gg);

    // ---- block reduce + single-pass finalize ----
    __shared__ float sT[8], sC[8], sK[8];
    if (lane == 0) { sT[warp] = tube; sC[warp] = ce; sK[warp] = kl; }
    __syncthreads();
    if (threadIdx.x == 0) {
        float t = 0.f, c = 0.f, k = 0.f;
#pragma unroll
        for (int i = 0; i < 8; i++) { t += sT[i]; c += sC[i]; k += sK[i]; }
        atomicAdd(&g_acc[0], (double)t);
        atomicAdd(&g_acc[1], (double)c);
        atomicAdd(&g_acc[2], (double)k);
        __threadfence();
        unsigned prev = atomicAdd(&g_count, 1u);
        if (prev == gridDim.x - 1) {
            __threadfence();
            double tubeS = g_acc[0] / (double)B;                         // ALPHA = 1
            double ceS   = g_acc[1] / (double)B;
            double klS   = -0.5 * BETA * (g_acc[2] / ((double)B * (double)Z));
            out[0] = (float)(tubeS + ceS + klS);
            g_acc[0] = 0.0; g_acc[1] = 0.0; g_acc[2] = 0.0;
            g_count = 0u;
            __threadfence();
        }
    }
}

extern "C" void kernel_launch(void* const* d_in, const int* in_sizes, int n_in,
                              void* d_out, int out_size) {
    const float* fusion  = (const float*)d_in[0];
    const float* comple  = (const float*)d_in[1];
    const float* labels  = (const float*)d_in[2];
    const float* lab_enc = (const float*)d_in[3];
    const float* xA      = (const float*)d_in[4];
    const float* xAr     = (const float*)d_in[5];
    const float* xB      = (const float*)d_in[6];
    const float* xBr     = (const float*)d_in[7];
    const float* xC      = (const float*)d_in[8];
    const float* xCr     = (const float*)d_in[9];
    const float* mu      = (const float*)d_in[10];
    const float* lv      = (const float*)d_in[11];
    float* out = (float*)d_out;

    // 2 rows per block -> B/2 blocks
    loss_kernel<<<B / 2, 256>>>(fusion, comple, labels, lab_enc,
                                xA, xAr, xB, xBr, xC, xCr, mu, lv, out);
}

// round 5
// speedup vs baseline: 1.2773x; 1.2773x over previous
#include <cuda_runtime.h>
#include <math.h>

#define B 16384
#define C 100
#define D 512
#define Z 128
#define BETA 50000000.0
#define EPSF 1e-8f

// accumulators: [0] = tube ds sum, [1] = -logp sum, [2] = kl term sum
// statically zeroed; last block resets after use -> graph-replay safe
__device__ double g_acc[3] = {0.0, 0.0, 0.0};
__device__ unsigned g_count = 0u;

__device__ __forceinline__ float warp_sum(float v) {
#pragma unroll
    for (int o = 16; o; o >>= 1) v += __shfl_xor_sync(0xffffffffu, v, o);
    return v;
}

// scalar tail of TUBE given full-row dot, |p|^2, |g|^2
__device__ __forceinline__ float tube_scalar(float dot, float pp, float gg) {
    float p = sqrtf(pp);
    float g = sqrtf(gg);
    float denom = p * g;
    float cosine = (denom == 0.f) ? 0.f : (dot / denom);
    float s_s = 1.f - cosine * cosine;
    float sine = (s_s < 0.f) ? 0.f : sqrtf((s_s <= 0.f) ? EPSF : s_s);
    float gd = (g == 0.f) ? (g + EPSF) : g;
    float pc = p * cosine;
    float r_all = pc / gd;
    float ps = p * sine;
    float ds;
    if (r_all >= 1.f)       ds = 0.5f * (ps + fabsf(g - pc));
    else if (r_all >= 0.f)  ds = ps + fabsf(g - pc);
    else                    ds = 1.5f * fabsf(pc - g - ps);
    return -__logf(tanhf(1.f / ds));   // ds==0 -> inf -> tanh=1 -> 0, matches jax
}

__global__ void __launch_bounds__(256, 4)
loss_kernel(const float* __restrict__ fusion,
            const float* __restrict__ comple,
            const float* __restrict__ labels,
            const float* __restrict__ lab_enc,
            const float* __restrict__ xA,  const float* __restrict__ xAr,
            const float* __restrict__ xB,  const float* __restrict__ xBr,
            const float* __restrict__ xC,  const float* __restrict__ xCr,
            const float* __restrict__ mu,  const float* __restrict__ lv,
            float* __restrict__ out)
{
    const int warp = threadIdx.x >> 5;
    const int lane = threadIdx.x & 31;
    const int row  = blockIdx.x * (blockDim.x >> 5) + warp;

    float tube = 0.f, ce = 0.f, kl = 0.f;

    {
        const long rd = (long)row * D;
        const float4* att4[4] = { (const float4*)(xAr + rd), (const float4*)(xBr + rd),
                                  (const float4*)(xCr + rd), (const float4*)(comple + rd) };
        const float4* lab4[4] = { (const float4*)(xA + rd),  (const float4*)(xB + rd),
                                  (const float4*)(xC + rd),  (const float4*)(lab_enc + rd) };

        float dot[4], pp[4], gg[4];

        // ---- tube loads in 2 groups of 2 pairs: 16 LDG.128 in flight per group,
        //      only 6 live accumulators -> fits 64 regs at occupancy 4 ----
#pragma unroll
        for (int jg = 0; jg < 4; jg += 2) {
#pragma unroll
            for (int j = jg; j < jg + 2; j++) { dot[j] = 0.f; pp[j] = 0.f; gg[j] = 0.f; }
#pragma unroll
            for (int i = 0; i < 4; i++) {
#pragma unroll
                for (int j = jg; j < jg + 2; j++) {
                    float4 a = att4[j][lane + 32 * i];
                    float4 g = lab4[j][lane + 32 * i];
                    dot[j] += a.x * g.x + a.y * g.y + a.z * g.z + a.w * g.w;
                    pp [j] += a.x * a.x + a.y * a.y + a.z * a.z + a.w * a.w;
                    gg [j] += g.x * g.x + g.y * g.y + g.z * g.z + g.w * g.w;
                }
            }
        }

        // ---- KL loads (independent) ----
        float4 m = ((const float4*)(mu + (long)row * Z))[lane];
        float4 l = ((const float4*)(lv + (long)row * Z))[lane];
        float kpart = (1.f + l.x - m.x * m.x - __expf(l.x))
                    + (1.f + l.y - m.y * m.y - __expf(l.y))
                    + (1.f + l.z - m.z * m.z - __expf(l.z))
                    + (1.f + l.w - m.w * m.w - __expf(l.w));

        // ---- CE pass 1: max(fusion) + argmax(labels) ----
        const float* f  = fusion + (long)row * C;
        const float* lb = labels + (long)row * C;
        float fmax = -INFINITY;
        float lmax = -INFINITY;
        int   lidx = 0x7fffffff;
#pragma unroll
        for (int t = 0; t < 4; t++) {
            int i = lane + 32 * t;
            if (i < C) {
                float fv  = f[i];
                float lvv = lb[i];
                fmax = fmaxf(fmax, fv);
                if (lvv > lmax || (lvv == lmax && i < lidx)) { lmax = lvv; lidx = i; }
            }
        }

        // ---- all warp reductions back-to-back (pipelined shuffle chains) ----
#pragma unroll
        for (int j = 0; j < 4; j++) {
            dot[j] = warp_sum(dot[j]);
            pp [j] = warp_sum(pp [j]);
            gg [j] = warp_sum(gg [j]);
        }
        kl = warp_sum(kpart);
#pragma unroll
        for (int o = 16; o; o >>= 1) {
            fmax = fmaxf(fmax, __shfl_xor_sync(0xffffffffu, fmax, o));
            float ol = __shfl_xor_sync(0xffffffffu, lmax, o);
            int   oi = __shfl_xor_sync(0xffffffffu, lidx, o);
            if (ol > lmax || (ol == lmax && oi < lidx)) { lmax = ol; lidx = oi; }
        }

        // ---- scalar tails ----
#pragma unroll
        for (int j = 0; j < 4; j++)
            tube += tube_scalar(dot[j], pp[j], gg[j]);

        // CE pass 2: row hot in L1
        float se = 0.f;
#pragma unroll
        for (int t = 0; t < 4; t++) {
            int i = lane + 32 * t;
            if (i < C) se += __expf(f[i] - fmax);
        }
        se = warp_sum(se);
        ce = -(f[lidx] - fmax - __logf(se));
    }

    // ---- block reduce + single-pass finalize ----
    __shared__ float sT[8], sC[8], sK[8];
    if (lane == 0) { sT[warp] = tube; sC[warp] = ce; sK[warp] = kl; }
    __syncthreads();
    if (threadIdx.x == 0) {
        float t = 0.f, c = 0.f, k = 0.f;
#pragma unroll
        for (int i = 0; i < 8; i++) { t += sT[i]; c += sC[i]; k += sK[i]; }
        atomicAdd(&g_acc[0], (double)t);
        atomicAdd(&g_acc[1], (double)c);
        atomicAdd(&g_acc[2], (double)k);
        __threadfence();
        unsigned prev = atomicAdd(&g_count, 1u);
        if (prev == gridDim.x - 1) {
            __threadfence();
            double tubeS = g_acc[0] / (double)B;                         // ALPHA = 1
            double ceS   = g_acc[1] / (double)B;
            double klS   = -0.5 * BETA * (g_acc[2] / ((double)B * (double)Z));
            out[0] = (float)(tubeS + ceS + klS);
            g_acc[0] = 0.0; g_acc[1] = 0.0; g_acc[2] = 0.0;
            g_count = 0u;
            __threadfence();
        }
    }
}

extern "C" void kernel_launch(void* const* d_in, const int* in_sizes, int n_in,
                              void* d_out, int out_size) {
    const float* fusion  = (const float*)d_in[0];
    const float* comple  = (const float*)d_in[1];
    const float* labels  = (const float*)d_in[2];
    const float* lab_enc = (const float*)d_in[3];
    const float* xA      = (const float*)d_in[4];
    const float* xAr     = (const float*)d_in[5];
    const float* xB      = (const float*)d_in[6];
    const float* xBr     = (const float*)d_in[7];
    const float* xC      = (const float*)d_in[8];
    const float* xCr     = (const float*)d_in[9];
    const float* mu      = (const float*)d_in[10];
    const float* lv      = (const float*)d_in[11];
    float* out = (float*)d_out;

    // 8 warps/block, 1 row/warp -> B/8 = 2048 blocks
    loss_kernel<<<B / 8, 256>>>(fusion, comple, labels, lab_enc,
                                xA, xAr, xB, xBr, xC, xCr, mu, lv, out);
}